// round 1
// baseline (speedup 1.0000x reference)
#include <cuda_runtime.h>
#include <math.h>
#include <stdint.h>

// Problem constants
#define BB   2
#define SS   2048
#define HH   2048
#define NHH  16
#define HD   128
#define MR   (BB*SS)        // 4096 rows

// ---------------- scratch (device globals; no allocation allowed) ----------
__device__ float g_ln [(size_t)MR * HH];          //  33.5 MB
__device__ float g_qkv[(size_t)MR * 3 * HH];      // 100.7 MB
__device__ float g_av [(size_t)MR * HH];          //  33.5 MB
__device__ float g_h  [(size_t)MR * HH];          //  33.5 MB
__device__ float g_mid[(size_t)MR * 4 * HH];      // 134.2 MB

// ---------------- LayerNorm: one block per row, two-pass -------------------
__global__ void ln_kernel(const float* __restrict__ x,
                          const float* __restrict__ w,
                          const float* __restrict__ b,
                          float* __restrict__ y)
{
    const int row = blockIdx.x;
    const float* xr = x + (size_t)row * HH;
    float* yr = y + (size_t)row * HH;
    const int t = threadIdx.x;

    __shared__ float red[8];
    __shared__ float bc;

    // pass 1: mean
    float s = 0.f;
    for (int i = t; i < HH; i += 256) s += xr[i];
    #pragma unroll
    for (int o = 16; o; o >>= 1) s += __shfl_xor_sync(0xffffffffu, s, o);
    if ((t & 31) == 0) red[t >> 5] = s;
    __syncthreads();
    if (t == 0) {
        float v = 0.f;
        #pragma unroll
        for (int i = 0; i < 8; i++) v += red[i];
        bc = v;
    }
    __syncthreads();
    const float mu = bc * (1.0f / HH);

    // pass 2: variance
    float vs = 0.f;
    for (int i = t; i < HH; i += 256) { float d = xr[i] - mu; vs += d * d; }
    #pragma unroll
    for (int o = 16; o; o >>= 1) vs += __shfl_xor_sync(0xffffffffu, vs, o);
    __syncthreads();                  // protect red[] reuse
    if ((t & 31) == 0) red[t >> 5] = vs;
    __syncthreads();
    if (t == 0) {
        float v = 0.f;
        #pragma unroll
        for (int i = 0; i < 8; i++) v += red[i];
        bc = v;
    }
    __syncthreads();
    const float rstd = rsqrtf(bc * (1.0f / HH) + 1e-5f);

    for (int i = t; i < HH; i += 256)
        yr[i] = (xr[i] - mu) * rstd * w[i] + b[i];
}

// ---------------- GEMM: C[M,N] = A[M,K] @ W[N,K]^T + bias (+epilogue) ------
// EPI 0: none   1: + res[M,N]   2: exact GELU
template<int EPI>
__global__ void __launch_bounds__(256, 2)
gemm_nt(const float* __restrict__ A, const float* __restrict__ W,
        const float* __restrict__ bias, const float* __restrict__ res,
        float* __restrict__ C, int M, int N, int K)
{
    __shared__ float As[16][128];
    __shared__ float Bs[16][128];

    const int t  = threadIdx.x;
    const int m0 = blockIdx.y * 128;
    const int n0 = blockIdx.x * 128;
    const int ty = t >> 4;          // 0..15
    const int tx = t & 15;          // 0..15

    // load mapping: each thread moves 2 float4 per operand per k-step
    const int lr  = t >> 2;         // row in tile (0..63), +64 for second
    const int lk  = (t & 3) << 2;   // k offset 0,4,8,12

    const float* Ap = A + (size_t)m0 * K;
    const float* Wp = W + (size_t)n0 * K;

    float acc[8][8];
    #pragma unroll
    for (int i = 0; i < 8; i++)
        #pragma unroll
        for (int j = 0; j < 8; j++) acc[i][j] = 0.f;

    for (int k0 = 0; k0 < K; k0 += 16) {
        float4 a0 = *(const float4*)(Ap + (size_t)lr        * K + k0 + lk);
        float4 a1 = *(const float4*)(Ap + (size_t)(lr + 64) * K + k0 + lk);
        float4 b0 = *(const float4*)(Wp + (size_t)lr        * K + k0 + lk);
        float4 b1 = *(const float4*)(Wp + (size_t)(lr + 64) * K + k0 + lk);

        __syncthreads();   // previous iteration's consumers done
        As[lk+0][lr]    = a0.x; As[lk+1][lr]    = a0.y; As[lk+2][lr]    = a0.z; As[lk+3][lr]    = a0.w;
        As[lk+0][lr+64] = a1.x; As[lk+1][lr+64] = a1.y; As[lk+2][lr+64] = a1.z; As[lk+3][lr+64] = a1.w;
        Bs[lk+0][lr]    = b0.x; Bs[lk+1][lr]    = b0.y; Bs[lk+2][lr]    = b0.z; Bs[lk+3][lr]    = b0.w;
        Bs[lk+0][lr+64] = b1.x; Bs[lk+1][lr+64] = b1.y; Bs[lk+2][lr+64] = b1.z; Bs[lk+3][lr+64] = b1.w;
        __syncthreads();

        #pragma unroll
        for (int kk = 0; kk < 16; kk++) {
            float4 A0 = *(const float4*)&As[kk][ty*8];
            float4 A1 = *(const float4*)&As[kk][ty*8 + 4];
            float4 B0 = *(const float4*)&Bs[kk][tx*8];
            float4 B1 = *(const float4*)&Bs[kk][tx*8 + 4];
            float ar[8] = {A0.x,A0.y,A0.z,A0.w,A1.x,A1.y,A1.z,A1.w};
            float br[8] = {B0.x,B0.y,B0.z,B0.w,B1.x,B1.y,B1.z,B1.w};
            #pragma unroll
            for (int i = 0; i < 8; i++)
                #pragma unroll
                for (int j = 0; j < 8; j++)
                    acc[i][j] = fmaf(ar[i], br[j], acc[i][j]);
        }
    }

    // epilogue
    float4 bb0 = *(const float4*)&bias[n0 + tx*8];
    float4 bb1 = *(const float4*)&bias[n0 + tx*8 + 4];
    float bv[8] = {bb0.x,bb0.y,bb0.z,bb0.w,bb1.x,bb1.y,bb1.z,bb1.w};

    #pragma unroll
    for (int i = 0; i < 8; i++) {
        const int gm = m0 + ty*8 + i;
        const size_t off = (size_t)gm * N + n0 + tx*8;
        float o[8];
        #pragma unroll
        for (int j = 0; j < 8; j++) o[j] = acc[i][j] + bv[j];
        if (EPI == 1) {
            float4 r0 = *(const float4*)&res[off];
            float4 r1 = *(const float4*)&res[off + 4];
            o[0]+=r0.x; o[1]+=r0.y; o[2]+=r0.z; o[3]+=r0.w;
            o[4]+=r1.x; o[5]+=r1.y; o[6]+=r1.z; o[7]+=r1.w;
        }
        if (EPI == 2) {
            #pragma unroll
            for (int j = 0; j < 8; j++)
                o[j] = 0.5f * o[j] * (1.0f + erff(o[j] * 0.70710678118654752f));
        }
        *(float4*)&C[off]     = make_float4(o[0],o[1],o[2],o[3]);
        *(float4*)&C[off + 4] = make_float4(o[4],o[5],o[6],o[7]);
    }
}

// ---------------- Flash attention (causal, additive -1e4 mask) -------------
// grid: (S/64, B*NH), 256 threads. hd = 128.
#define ATTN_SMEM_FLOATS (2*64*129 + 64*128 + 64*65)
#define ATTN_SMEM_BYTES  (ATTN_SMEM_FLOATS * 4)

__global__ void __launch_bounds__(256, 1)
attn_kernel(const float* __restrict__ qkv, float* __restrict__ av)
{
    extern __shared__ float sm[];
    float (*sQ)[129] = (float(*)[129])(sm);
    float (*sK)[129] = (float(*)[129])(sm + 64*129);
    float (*sV)[128] = (float(*)[128])(sm + 2*64*129);
    float (*sP)[65]  = (float(*)[65]) (sm + 2*64*129 + 64*128);

    const int t  = threadIdx.x;
    const int qt = blockIdx.x;
    const int bh = blockIdx.y;
    const int b  = bh >> 4;
    const int h  = bh & 15;
    const int qbase = qt * 64;

    const size_t rstr = (size_t)3 * HH;
    const float* base = qkv + (size_t)b * SS * rstr;
    const int qoff = h * HD;
    const int koff = HH + h * HD;
    const int voff = 2 * HH + h * HD;

    // load Q tile (64 x 128)
    for (int i = t; i < 2048; i += 256) {
        int r  = i >> 5;
        int c4 = (i & 31) << 2;
        float4 v = *(const float4*)(base + (size_t)(qbase + r) * rstr + qoff + c4);
        sQ[r][c4+0]=v.x; sQ[r][c4+1]=v.y; sQ[r][c4+2]=v.z; sQ[r][c4+3]=v.w;
    }

    const int rg = t >> 4;          // row group 0..15
    const int cg = t & 15;
    const int r0  = rg * 4;
    const int c0  = cg * 4;         // score cols
    const int c0o = cg * 8;         // output cols

    float m[4], l[4], acc[4][8];
    #pragma unroll
    for (int i = 0; i < 4; i++) {
        m[i] = -1e30f; l[i] = 0.f;
        #pragma unroll
        for (int j = 0; j < 8; j++) acc[i][j] = 0.f;
    }

    const float rsd = 0.08838834764831845f;   // 1/sqrt(128)

    for (int kt = 0; kt <= qt; kt++) {
        const int kbase = kt * 64;
        __syncthreads();            // Q load / previous O-update complete
        for (int i = t; i < 2048; i += 256) {
            int r  = i >> 5;
            int c4 = (i & 31) << 2;
            const float* rp = base + (size_t)(kbase + r) * rstr;
            float4 kv = *(const float4*)(rp + koff + c4);
            sK[r][c4+0]=kv.x; sK[r][c4+1]=kv.y; sK[r][c4+2]=kv.z; sK[r][c4+3]=kv.w;
            float4 vv = *(const float4*)(rp + voff + c4);
            *(float4*)&sV[r][c4] = vv;
        }
        __syncthreads();

        // S = Q K^T
        float s[4][4];
        #pragma unroll
        for (int i = 0; i < 4; i++)
            #pragma unroll
            for (int c = 0; c < 4; c++) s[i][c] = 0.f;

        #pragma unroll 4
        for (int d = 0; d < 128; d++) {
            float k0v = sK[c0+0][d], k1v = sK[c0+1][d], k2v = sK[c0+2][d], k3v = sK[c0+3][d];
            #pragma unroll
            for (int i = 0; i < 4; i++) {
                float q = sQ[r0+i][d];
                s[i][0] = fmaf(q, k0v, s[i][0]);
                s[i][1] = fmaf(q, k1v, s[i][1]);
                s[i][2] = fmaf(q, k2v, s[i][2]);
                s[i][3] = fmaf(q, k3v, s[i][3]);
            }
        }

        // scale + causal mask (additive -1e4 like the reference)
        #pragma unroll
        for (int i = 0; i < 4; i++) {
            const int qi = qbase + r0 + i;
            #pragma unroll
            for (int c = 0; c < 4; c++) {
                s[i][c] *= rsd;
                if (kbase + c0 + c > qi) s[i][c] -= 1e4f;
            }
        }

        // online softmax (stats replicated over the 16 lanes of a row group)
        #pragma unroll
        for (int i = 0; i < 4; i++) {
            float tm = fmaxf(fmaxf(s[i][0], s[i][1]), fmaxf(s[i][2], s[i][3]));
            #pragma unroll
            for (int o = 8; o; o >>= 1) tm = fmaxf(tm, __shfl_xor_sync(0xffffffffu, tm, o));
            float nm = fmaxf(m[i], tm);
            float sc = __expf(m[i] - nm);
            float p0 = __expf(s[i][0] - nm);
            float p1 = __expf(s[i][1] - nm);
            float p2 = __expf(s[i][2] - nm);
            float p3 = __expf(s[i][3] - nm);
            sP[r0+i][c0+0] = p0; sP[r0+i][c0+1] = p1;
            sP[r0+i][c0+2] = p2; sP[r0+i][c0+3] = p3;
            float rs = p0 + p1 + p2 + p3;
            #pragma unroll
            for (int o = 8; o; o >>= 1) rs += __shfl_xor_sync(0xffffffffu, rs, o);
            l[i] = l[i] * sc + rs;
            m[i] = nm;
            #pragma unroll
            for (int j = 0; j < 8; j++) acc[i][j] *= sc;
        }
        __syncthreads();

        // O += P @ V
        #pragma unroll 2
        for (int j = 0; j < 64; j++) {
            float4 va = *(const float4*)&sV[j][c0o];
            float4 vb = *(const float4*)&sV[j][c0o + 4];
            #pragma unroll
            for (int i = 0; i < 4; i++) {
                float p = sP[r0+i][j];
                acc[i][0] = fmaf(p, va.x, acc[i][0]);
                acc[i][1] = fmaf(p, va.y, acc[i][1]);
                acc[i][2] = fmaf(p, va.z, acc[i][2]);
                acc[i][3] = fmaf(p, va.w, acc[i][3]);
                acc[i][4] = fmaf(p, vb.x, acc[i][4]);
                acc[i][5] = fmaf(p, vb.y, acc[i][5]);
                acc[i][6] = fmaf(p, vb.z, acc[i][6]);
                acc[i][7] = fmaf(p, vb.w, acc[i][7]);
            }
        }
    }

    // write output
    #pragma unroll
    for (int i = 0; i < 4; i++) {
        const int qi = qbase + r0 + i;
        const float inv = 1.0f / l[i];
        float* op = av + ((size_t)(b * SS + qi)) * HH + h * HD + c0o;
        *(float4*)op       = make_float4(acc[i][0]*inv, acc[i][1]*inv, acc[i][2]*inv, acc[i][3]*inv);
        *(float4*)(op + 4) = make_float4(acc[i][4]*inv, acc[i][5]*inv, acc[i][6]*inv, acc[i][7]*inv);
    }
}

// ---------------- launcher --------------------------------------------------
extern "C" void kernel_launch(void* const* d_in, const int* in_sizes, int n_in,
                              void* d_out, int out_size)
{
    const float* x      = (const float*)d_in[0];
    const float* ln1_w  = (const float*)d_in[1];
    const float* ln1_b  = (const float*)d_in[2];
    const float* wqkv_w = (const float*)d_in[3];
    const float* wqkv_b = (const float*)d_in[4];
    const float* wo_w   = (const float*)d_in[5];
    const float* wo_b   = (const float*)d_in[6];
    const float* ln2_w  = (const float*)d_in[7];
    const float* ln2_b  = (const float*)d_in[8];
    const float* w1     = (const float*)d_in[9];
    const float* b1     = (const float*)d_in[10];
    const float* w2     = (const float*)d_in[11];
    const float* b2     = (const float*)d_in[12];
    float* out = (float*)d_out;

    float *ln, *qkv, *av, *h, *mid;
    cudaGetSymbolAddress((void**)&ln,  g_ln);
    cudaGetSymbolAddress((void**)&qkv, g_qkv);
    cudaGetSymbolAddress((void**)&av,  g_av);
    cudaGetSymbolAddress((void**)&h,   g_h);
    cudaGetSymbolAddress((void**)&mid, g_mid);

    cudaFuncSetAttribute(attn_kernel,
                         cudaFuncAttributeMaxDynamicSharedMemorySize,
                         ATTN_SMEM_BYTES);

    // 1. ln1(x)
    ln_kernel<<<MR, 256>>>(x, ln1_w, ln1_b, ln);
    // 2. qkv = ln @ Wqkv^T + b
    gemm_nt<0><<<dim3(3*HH/128, MR/128), 256>>>(ln, wqkv_w, wqkv_b, nullptr, qkv,
                                                MR, 3*HH, HH);
    // 3. av = attention(qkv)
    attn_kernel<<<dim3(SS/64, BB*NHH), 256, ATTN_SMEM_BYTES>>>(qkv, av);
    // 4. h = x + av @ Wo^T + b
    gemm_nt<1><<<dim3(HH/128, MR/128), 256>>>(av, wo_w, wo_b, x, h,
                                              MR, HH, HH);
    // 5. ln2(h)
    ln_kernel<<<MR, 256>>>(h, ln2_w, ln2_b, ln);
    // 6. mid = gelu(ln @ W1^T + b1)
    gemm_nt<2><<<dim3(4*HH/128, MR/128), 256>>>(ln, w1, b1, nullptr, mid,
                                                MR, 4*HH, HH);
    // 7. out = h + mid @ W2^T + b2
    gemm_nt<1><<<dim3(HH/128, MR/128), 256>>>(mid, w2, b2, h, out,
                                              MR, HH, 4*HH);
}

// round 3
// speedup vs baseline: 1.8235x; 1.8235x over previous
#include <cuda_runtime.h>
#include <math.h>
#include <stdint.h>

// Problem constants
#define BB   2
#define SS   2048
#define HH   2048
#define NHH  16
#define HD   128
#define MR   (BB*SS)        // 4096 rows

// ---------------- scratch (device globals; no allocation allowed) ----------
__device__ float g_ln [(size_t)MR * HH];
__device__ float g_qkv[(size_t)MR * 3 * HH];
__device__ float g_av [(size_t)MR * HH];
__device__ float g_h  [(size_t)MR * HH];
__device__ float g_mid[(size_t)MR * 4 * HH];

// ---------------- helpers ---------------------------------------------------
__device__ __forceinline__ uint32_t f2tf32(float f) {
    uint32_t u;
    asm("cvt.rna.tf32.f32 %0, %1;" : "=r"(u) : "f"(f));
    return u;
}

// mma.sync m16n8k8 tf32: D = A*B + D
__device__ __forceinline__ void mma_tf32(float c[4],
                                         uint32_t a0, uint32_t a1, uint32_t a2, uint32_t a3,
                                         uint32_t b0, uint32_t b1) {
    asm volatile(
        "mma.sync.aligned.m16n8k8.row.col.f32.tf32.tf32.f32 "
        "{%0,%1,%2,%3}, {%4,%5,%6,%7}, {%8,%9}, {%0,%1,%2,%3};"
        : "+f"(c[0]), "+f"(c[1]), "+f"(c[2]), "+f"(c[3])
        : "r"(a0), "r"(a1), "r"(a2), "r"(a3), "r"(b0), "r"(b1));
}

// ======================= tf32 mma.sync GEMM ================================
// C[M,N] = A[M,K] @ W[N,K]^T + bias   EPI: 0 none, 1 +res, 2 exact GELU
// CTA tile 128x128, K-chunk 32, double-buffered. 8 warps: 2(M) x 4(N),
// each warp computes 64x32 via 4x4 m16n8k8 atoms.
// Shared layout (floats), per stage (8192 floats = 32KB):
//   A frags: [mtile 0..7][kk 0..3][lane 0..31][reg 0..3]   (4096 floats)
//   B frags: [ntile 0..15][kk 0..3][lane 0..31][reg 0..1]  (4096 floats)
#define GEMM_SMEM_FLOATS (2 * 8192)
#define GEMM_SMEM_BYTES  (GEMM_SMEM_FLOATS * 4)

template<int EPI>
__global__ void __launch_bounds__(256)
gemm_mma(const float* __restrict__ A, const float* __restrict__ W,
         const float* __restrict__ bias, const float* __restrict__ res,
         float* __restrict__ C, int M, int N, int K)
{
    extern __shared__ float sm[];
    const int t    = threadIdx.x;
    const int lane = t & 31;
    const int wid  = t >> 5;
    const int warp_m = wid >> 2;       // 0..1
    const int warp_n = wid & 3;        // 0..3
    const int m0 = blockIdx.y * 128;
    const int n0 = blockIdx.x * 128;

    const float* Ap = A + (size_t)m0 * K;
    const float* Wp = W + (size_t)n0 * K;

    // producer mapping: thread handles rows {it*32 + t/8}, k-quad (t%8)*4
    const int prow = t >> 3;           // 0..31
    const int kq   = (t & 7) << 2;     // 0,4,...,28

    float acc[4][4][4];
    #pragma unroll
    for (int m = 0; m < 4; m++)
        #pragma unroll
        for (int n = 0; n < 4; n++)
            #pragma unroll
            for (int r = 0; r < 4; r++) acc[m][n][r] = 0.f;

    float4 av[4], wv[4];

    auto GLOAD = [&](int ch) {
        const int k0 = ch * 32;
        #pragma unroll
        for (int it = 0; it < 4; it++) {
            const int r = it * 32 + prow;
            av[it] = *(const float4*)(Ap + (size_t)r * K + k0 + kq);
            wv[it] = *(const float4*)(Wp + (size_t)r * K + k0 + kq);
        }
    };

    auto STS = [&](int stage) {
        float* sA = sm + stage * 8192;
        float* sB = sA + 4096;
        #pragma unroll
        for (int it = 0; it < 4; it++) {
            const int row = it * 32 + prow;
            const int rr = row & 15, mtile = row >> 4;
            const int nn = row & 7,  ntile = row >> 3;
            float a[4] = {av[it].x, av[it].y, av[it].z, av[it].w};
            float w[4] = {wv[it].x, wv[it].y, wv[it].z, wv[it].w};
            #pragma unroll
            for (int j = 0; j < 4; j++) {
                const int k  = kq + j;
                const int kk = k >> 3, cc = k & 7;
                const int laneA = (rr & 7) * 4 + (cc & 3);
                const int regA  = (rr >> 3) + ((cc >> 2) << 1);
                sA[((mtile * 4 + kk) * 32 + laneA) * 4 + regA] = __uint_as_float(f2tf32(a[j]));
                const int laneB = nn * 4 + (cc & 3);
                const int regB  = cc >> 2;
                sB[((ntile * 4 + kk) * 32 + laneB) * 2 + regB] = __uint_as_float(f2tf32(w[j]));
            }
        }
    };

    auto CONSUME = [&](int stage) {
        const float* sA = sm + stage * 8192;
        const float* sB = sA + 4096;
        #pragma unroll
        for (int kk = 0; kk < 4; kk++) {
            uint4 af[4];
            uint2 bf[4];
            #pragma unroll
            for (int m = 0; m < 4; m++)
                af[m] = *(const uint4*)&sA[(((warp_m * 4 + m) * 4 + kk) * 32 + lane) * 4];
            #pragma unroll
            for (int n = 0; n < 4; n++)
                bf[n] = *(const uint2*)&sB[(((warp_n * 4 + n) * 4 + kk) * 32 + lane) * 2];
            #pragma unroll
            for (int m = 0; m < 4; m++)
                #pragma unroll
                for (int n = 0; n < 4; n++)
                    mma_tf32(acc[m][n], af[m].x, af[m].y, af[m].z, af[m].w,
                             bf[n].x, bf[n].y);
        }
    };

    const int nch = K >> 5;
    GLOAD(0);
    STS(0);
    __syncthreads();
    int stage = 0;
    for (int ch = 0; ch < nch; ch++) {
        const bool more = (ch + 1 < nch);
        if (more) GLOAD(ch + 1);
        CONSUME(stage);
        if (more) STS(stage ^ 1);
        __syncthreads();
        stage ^= 1;
    }

    // ---------------- epilogue ------------------------------------------------
    const int gid = lane >> 2;         // 0..7
    const int tig = lane & 3;          // 0..3
    #pragma unroll
    for (int n = 0; n < 4; n++) {
        const int col = n0 + (warp_n * 4 + n) * 8 + tig * 2;
        const float2 bv = *(const float2*)&bias[col];
        #pragma unroll
        for (int m = 0; m < 4; m++) {
            const int rowa = m0 + (warp_m * 4 + m) * 16 + gid;
            const size_t offa = (size_t)rowa * N + col;
            const size_t offb = offa + (size_t)8 * N;
            float o0 = acc[m][n][0] + bv.x;
            float o1 = acc[m][n][1] + bv.y;
            float o2 = acc[m][n][2] + bv.x;
            float o3 = acc[m][n][3] + bv.y;
            if (EPI == 1) {
                float2 r0 = *(const float2*)&res[offa];
                float2 r1 = *(const float2*)&res[offb];
                o0 += r0.x; o1 += r0.y; o2 += r1.x; o3 += r1.y;
            }
            if (EPI == 2) {
                o0 = 0.5f * o0 * (1.0f + erff(o0 * 0.70710678118654752f));
                o1 = 0.5f * o1 * (1.0f + erff(o1 * 0.70710678118654752f));
                o2 = 0.5f * o2 * (1.0f + erff(o2 * 0.70710678118654752f));
                o3 = 0.5f * o3 * (1.0f + erff(o3 * 0.70710678118654752f));
            }
            *(float2*)&C[offa] = make_float2(o0, o1);
            *(float2*)&C[offb] = make_float2(o2, o3);
        }
    }
}

// ---------------- LayerNorm: one block per row, two-pass -------------------
__global__ void ln_kernel(const float* __restrict__ x,
                          const float* __restrict__ w,
                          const float* __restrict__ b,
                          float* __restrict__ y)
{
    const int row = blockIdx.x;
    const float* xr = x + (size_t)row * HH;
    float* yr = y + (size_t)row * HH;
    const int t = threadIdx.x;

    __shared__ float red[8];
    __shared__ float bc;

    float s = 0.f;
    for (int i = t; i < HH; i += 256) s += xr[i];
    #pragma unroll
    for (int o = 16; o; o >>= 1) s += __shfl_xor_sync(0xffffffffu, s, o);
    if ((t & 31) == 0) red[t >> 5] = s;
    __syncthreads();
    if (t == 0) {
        float v = 0.f;
        #pragma unroll
        for (int i = 0; i < 8; i++) v += red[i];
        bc = v;
    }
    __syncthreads();
    const float mu = bc * (1.0f / HH);

    float vs = 0.f;
    for (int i = t; i < HH; i += 256) { float d = xr[i] - mu; vs += d * d; }
    #pragma unroll
    for (int o = 16; o; o >>= 1) vs += __shfl_xor_sync(0xffffffffu, vs, o);
    __syncthreads();
    if ((t & 31) == 0) red[t >> 5] = vs;
    __syncthreads();
    if (t == 0) {
        float v = 0.f;
        #pragma unroll
        for (int i = 0; i < 8; i++) v += red[i];
        bc = v;
    }
    __syncthreads();
    const float rstd = rsqrtf(bc * (1.0f / HH) + 1e-5f);

    for (int i = t; i < HH; i += 256)
        yr[i] = (xr[i] - mu) * rstd * w[i] + b[i];
}

// ---------------- Flash attention (causal, additive -1e4 mask) -------------
#define ATTN_SMEM_FLOATS (2*64*129 + 64*128 + 64*65)
#define ATTN_SMEM_BYTES  (ATTN_SMEM_FLOATS * 4)

__global__ void __launch_bounds__(256, 1)
attn_kernel(const float* __restrict__ qkv, float* __restrict__ av)
{
    extern __shared__ float sma[];
    float (*sQ)[129] = (float(*)[129])(sma);
    float (*sK)[129] = (float(*)[129])(sma + 64*129);
    float (*sV)[128] = (float(*)[128])(sma + 2*64*129);
    float (*sP)[65]  = (float(*)[65]) (sma + 2*64*129 + 64*128);

    const int t  = threadIdx.x;
    const int qt = blockIdx.x;
    const int bh = blockIdx.y;
    const int b  = bh >> 4;
    const int h  = bh & 15;
    const int qbase = qt * 64;

    const size_t rstr = (size_t)3 * HH;
    const float* base = qkv + (size_t)b * SS * rstr;
    const int qoff = h * HD;
    const int koff = HH + h * HD;
    const int voff = 2 * HH + h * HD;

    for (int i = t; i < 2048; i += 256) {
        int r  = i >> 5;
        int c4 = (i & 31) << 2;
        float4 v = *(const float4*)(base + (size_t)(qbase + r) * rstr + qoff + c4);
        sQ[r][c4+0]=v.x; sQ[r][c4+1]=v.y; sQ[r][c4+2]=v.z; sQ[r][c4+3]=v.w;
    }

    const int rg = t >> 4;
    const int cg = t & 15;
    const int r0  = rg * 4;
    const int c0  = cg * 4;
    const int c0o = cg * 8;

    float m[4], l[4], acc[4][8];
    #pragma unroll
    for (int i = 0; i < 4; i++) {
        m[i] = -1e30f; l[i] = 0.f;
        #pragma unroll
        for (int j = 0; j < 8; j++) acc[i][j] = 0.f;
    }

    const float rsd = 0.08838834764831845f;

    for (int kt = 0; kt <= qt; kt++) {
        const int kbase = kt * 64;
        __syncthreads();
        for (int i = t; i < 2048; i += 256) {
            int r  = i >> 5;
            int c4 = (i & 31) << 2;
            const float* rp = base + (size_t)(kbase + r) * rstr;
            float4 kv = *(const float4*)(rp + koff + c4);
            sK[r][c4+0]=kv.x; sK[r][c4+1]=kv.y; sK[r][c4+2]=kv.z; sK[r][c4+3]=kv.w;
            float4 vv = *(const float4*)(rp + voff + c4);
            *(float4*)&sV[r][c4] = vv;
        }
        __syncthreads();

        float s[4][4];
        #pragma unroll
        for (int i = 0; i < 4; i++)
            #pragma unroll
            for (int c = 0; c < 4; c++) s[i][c] = 0.f;

        #pragma unroll 4
        for (int d = 0; d < 128; d++) {
            float k0v = sK[c0+0][d], k1v = sK[c0+1][d], k2v = sK[c0+2][d], k3v = sK[c0+3][d];
            #pragma unroll
            for (int i = 0; i < 4; i++) {
                float q = sQ[r0+i][d];
                s[i][0] = fmaf(q, k0v, s[i][0]);
                s[i][1] = fmaf(q, k1v, s[i][1]);
                s[i][2] = fmaf(q, k2v, s[i][2]);
                s[i][3] = fmaf(q, k3v, s[i][3]);
            }
        }

        #pragma unroll
        for (int i = 0; i < 4; i++) {
            const int qi = qbase + r0 + i;
            #pragma unroll
            for (int c = 0; c < 4; c++) {
                s[i][c] *= rsd;
                if (kbase + c0 + c > qi) s[i][c] -= 1e4f;
            }
        }

        #pragma unroll
        for (int i = 0; i < 4; i++) {
            float tm = fmaxf(fmaxf(s[i][0], s[i][1]), fmaxf(s[i][2], s[i][3]));
            #pragma unroll
            for (int o = 8; o; o >>= 1) tm = fmaxf(tm, __shfl_xor_sync(0xffffffffu, tm, o));
            float nm = fmaxf(m[i], tm);
            float sc = __expf(m[i] - nm);
            float p0 = __expf(s[i][0] - nm);
            float p1 = __expf(s[i][1] - nm);
            float p2 = __expf(s[i][2] - nm);
            float p3 = __expf(s[i][3] - nm);
            sP[r0+i][c0+0] = p0; sP[r0+i][c0+1] = p1;
            sP[r0+i][c0+2] = p2; sP[r0+i][c0+3] = p3;
            float rs = p0 + p1 + p2 + p3;
            #pragma unroll
            for (int o = 8; o; o >>= 1) rs += __shfl_xor_sync(0xffffffffu, rs, o);
            l[i] = l[i] * sc + rs;
            m[i] = nm;
            #pragma unroll
            for (int j = 0; j < 8; j++) acc[i][j] *= sc;
        }
        __syncthreads();

        #pragma unroll 2
        for (int j = 0; j < 64; j++) {
            float4 va = *(const float4*)&sV[j][c0o];
            float4 vb = *(const float4*)&sV[j][c0o + 4];
            #pragma unroll
            for (int i = 0; i < 4; i++) {
                float p = sP[r0+i][j];
                acc[i][0] = fmaf(p, va.x, acc[i][0]);
                acc[i][1] = fmaf(p, va.y, acc[i][1]);
                acc[i][2] = fmaf(p, va.z, acc[i][2]);
                acc[i][3] = fmaf(p, va.w, acc[i][3]);
                acc[i][4] = fmaf(p, vb.x, acc[i][4]);
                acc[i][5] = fmaf(p, vb.y, acc[i][5]);
                acc[i][6] = fmaf(p, vb.z, acc[i][6]);
                acc[i][7] = fmaf(p, vb.w, acc[i][7]);
            }
        }
    }

    #pragma unroll
    for (int i = 0; i < 4; i++) {
        const int qi = qbase + r0 + i;
        const float inv = 1.0f / l[i];
        float* op = av + ((size_t)(b * SS + qi)) * HH + h * HD + c0o;
        *(float4*)op       = make_float4(acc[i][0]*inv, acc[i][1]*inv, acc[i][2]*inv, acc[i][3]*inv);
        *(float4*)(op + 4) = make_float4(acc[i][4]*inv, acc[i][5]*inv, acc[i][6]*inv, acc[i][7]*inv);
    }
}

// ---------------- launcher --------------------------------------------------
extern "C" void kernel_launch(void* const* d_in, const int* in_sizes, int n_in,
                              void* d_out, int out_size)
{
    const float* x      = (const float*)d_in[0];
    const float* ln1_w  = (const float*)d_in[1];
    const float* ln1_b  = (const float*)d_in[2];
    const float* wqkv_w = (const float*)d_in[3];
    const float* wqkv_b = (const float*)d_in[4];
    const float* wo_w   = (const float*)d_in[5];
    const float* wo_b   = (const float*)d_in[6];
    const float* ln2_w  = (const float*)d_in[7];
    const float* ln2_b  = (const float*)d_in[8];
    const float* w1     = (const float*)d_in[9];
    const float* b1     = (const float*)d_in[10];
    const float* w2     = (const float*)d_in[11];
    const float* b2     = (const float*)d_in[12];
    float* out = (float*)d_out;

    float *ln, *qkv, *av, *h, *mid;
    cudaGetSymbolAddress((void**)&ln,  g_ln);
    cudaGetSymbolAddress((void**)&qkv, g_qkv);
    cudaGetSymbolAddress((void**)&av,  g_av);
    cudaGetSymbolAddress((void**)&h,   g_h);
    cudaGetSymbolAddress((void**)&mid, g_mid);

    cudaFuncSetAttribute(attn_kernel,
                         cudaFuncAttributeMaxDynamicSharedMemorySize, ATTN_SMEM_BYTES);
    cudaFuncSetAttribute(gemm_mma<0>,
                         cudaFuncAttributeMaxDynamicSharedMemorySize, GEMM_SMEM_BYTES);
    cudaFuncSetAttribute(gemm_mma<1>,
                         cudaFuncAttributeMaxDynamicSharedMemorySize, GEMM_SMEM_BYTES);
    cudaFuncSetAttribute(gemm_mma<2>,
                         cudaFuncAttributeMaxDynamicSharedMemorySize, GEMM_SMEM_BYTES);

    // 1. ln1(x)
    ln_kernel<<<MR, 256>>>(x, ln1_w, ln1_b, ln);
    // 2. qkv = ln @ Wqkv^T + b
    gemm_mma<0><<<dim3(3*HH/128, MR/128), 256, GEMM_SMEM_BYTES>>>(ln, wqkv_w, wqkv_b, nullptr, qkv,
                                                                  MR, 3*HH, HH);
    // 3. av = attention(qkv)
    attn_kernel<<<dim3(SS/64, BB*NHH), 256, ATTN_SMEM_BYTES>>>(qkv, av);
    // 4. h = x + av @ Wo^T + b
    gemm_mma<1><<<dim3(HH/128, MR/128), 256, GEMM_SMEM_BYTES>>>(av, wo_w, wo_b, x, h,
                                                                MR, HH, HH);
    // 5. ln2(h)
    ln_kernel<<<MR, 256>>>(h, ln2_w, ln2_b, ln);
    // 6. mid = gelu(ln @ W1^T + b1)
    gemm_mma<2><<<dim3(4*HH/128, MR/128), 256, GEMM_SMEM_BYTES>>>(ln, w1, b1, nullptr, mid,
                                                                  MR, 4*HH, HH);
    // 7. out = h + mid @ W2^T + b2
    gemm_mma<1><<<dim3(HH/128, MR/128), 256, GEMM_SMEM_BYTES>>>(mid, w2, b2, h, out,
                                                                MR, HH, 4*HH);
}